// round 9
// baseline (speedup 1.0000x reference)
#include <cuda_runtime.h>
#include <cuda_bf16.h>

#define EPS   1e-6f
#define NCOLS 4096
#define MAXB  8192
#define NBLK  444          // 148 SMs x 3 resident CTAs (persistent grid)

// Scratch (static __device__; no allocation). Packed warp segments:
// pref | suf<<9 | best<<18, each value <= 256 (9 bits).
__device__ unsigned g_seg[MAXB * 16];   // [row][warp]  (512 KB)
__device__ float    g_pw[NBLK];         // per-CTA sum of depth_weights * bce
__device__ unsigned int g_count = 0;

// Combine left (ap,as,ab | len la) with right (bp,bs,bb | len lb); result in a*.
#define SEG_COMBINE(ap, as, ab, la, bp, bs, bb, lb)              \
    do {                                                         \
        int _np = ((ap) == (la)) ? (la) + (bp) : (ap);           \
        int _ns = ((bs) == (lb)) ? (lb) + (as) : (bs);           \
        int _nb = max(max((ab), (bb)), (as) + (bp));             \
        (ap) = _np; (as) = _ns; (ab) = _nb;                      \
    } while (0)

__device__ __forceinline__ void unpack_seg(unsigned v, int& p, int& s, int& b) {
    p = v & 511; s = (v >> 9) & 511; b = (int)(v >> 18);
}

// Persistent CTAs: 512 threads (16 warps). Warps are fully independent in the
// main loop (NO barriers): warp w of the CTA handles float4 [w*64, (w+1)*64)
// of each row, lane i holding 8 contiguous elements (float4s 2i, 2i+1).
// Lane 0 stores the warp's packed 256-elem segment; cross-warp combine is
// deferred to the last-CTA tail.
__global__ __launch_bounds__(512, 3)
void depth_loss_fused_kernel(const float4* __restrict__ p4,
                             const float4* __restrict__ t4,
                             const float4* __restrict__ w4,
                             float* __restrict__ out, int B)
{
    const int tid  = threadIdx.x;
    const int warp = tid >> 5;
    const int lane = tid & 31;

    __shared__ int s_isLast;

    float wacc = 0.0f;            // per-thread bce partial across all its rows

    for (int row = blockIdx.x; row < B; row += gridDim.x) {
        const size_t base = (size_t)row * (NCOLS / 4) + warp * 64 + lane * 2;

        // front-batch all 6 LDG.128
        float4 pA = __ldcs(&p4[base]), pB = __ldcs(&p4[base + 1]);
        float4 tA = __ldcs(&t4[base]), tB = __ldcs(&t4[base + 1]);
        float4 wA = __ldcs(&w4[base]), wB = __ldcs(&w4[base + 1]);

        float pp[8] = {pA.x, pA.y, pA.z, pA.w, pB.x, pB.y, pB.z, pB.w};
        float tt[8] = {tA.x, tA.y, tA.z, tA.w, tB.x, tB.y, tB.z, tB.w};
        float ww[8] = {wA.x, wA.y, wA.z, wA.w, wB.x, wB.y, wB.z, wB.w};

        // leaf state over 8 contiguous elements (branch-free); bce into wacc
        int cur = 0, best = 0, pref = 0, all = 1;
#pragma unroll
        for (int e = 0; e < 8; e++) {
            bool tb = (tt[e] > 0.5f);
            bool pb = (pp[e] > 0.5f);
            int corr = (tb == pb) ? 1 : 0;
            float v = tb ? (pp[e] + EPS) : ((1.0f - pp[e]) + EPS);
            wacc = fmaf(ww[e], -__logf(v), wacc);
            cur  = corr ? (cur + 1) : 0;
            best = max(best, cur);
            all &= corr;
            pref += all;
        }
        int suf = cur;

        // warp tree: 8-elem leaves -> 256-elem warp segment (valid in lane 0)
#pragma unroll
        for (int s = 0; s < 5; s++) {
            int len = 8 << s;
            int op = __shfl_down_sync(0xffffffffu, pref, 1 << s);
            int os = __shfl_down_sync(0xffffffffu, suf,  1 << s);
            int ob = __shfl_down_sync(0xffffffffu, best, 1 << s);
            SEG_COMBINE(pref, suf, best, len, op, os, ob, len);
        }

        if (lane == 0)
            g_seg[row * 16 + warp] =
                (unsigned)pref | ((unsigned)suf << 9) | ((unsigned)best << 18);
    }

    // ---- CTA end: reduce per-thread bce partials, one fence+atomic per CTA ----
#pragma unroll
    for (int s = 16; s > 0; s >>= 1)
        wacc += __shfl_down_sync(0xffffffffu, wacc, s);
    __shared__ float shwf[16];
    if (lane == 0) shwf[warp] = wacc;
    __syncthreads();
    if (tid == 0) {
        float ws = shwf[0];
#pragma unroll
        for (int wi = 1; wi < 16; wi++) ws += shwf[wi];
        g_pw[blockIdx.x] = ws;
        __threadfence();                         // release segs + partial
        unsigned int done = atomicAdd(&g_count, 1u);
        s_isLast = (done == (unsigned int)(gridDim.x - 1)) ? 1 : 0;
    }
    __syncthreads();

    // ---- last CTA: per-row cross-warp combine + final deterministic reduce ----
    if (s_isLast) {
        __threadfence();   // acquire: see all CTAs' writes
        double dw = 0.0;
        long long dsi = 0;
        for (int i = tid; i < (int)gridDim.x; i += 512)
            dw += (double)g_pw[i];

        const uint4* seg4 = (const uint4*)g_seg;   // 4 x uint4 per row
        for (int r = tid; r < B; r += 512) {
            uint4 a = seg4[r * 4 + 0];
            uint4 b = seg4[r * 4 + 1];
            uint4 c = seg4[r * 4 + 2];
            uint4 d = seg4[r * 4 + 3];
            unsigned segs[16] = {a.x, a.y, a.z, a.w, b.x, b.y, b.z, b.w,
                                 c.x, c.y, c.z, c.w, d.x, d.y, d.z, d.w};
            int ap, as, ab;
            unpack_seg(segs[0], ap, as, ab);
#pragma unroll
            for (int wi = 1; wi < 16; wi++) {
                int bp, bs, bb;
                unpack_seg(segs[wi], bp, bs, bb);
                SEG_COMBINE(ap, as, ab, 256 * wi, bp, bs, bb, 256);
            }
            dsi += (long long)ab;
        }

        __shared__ double    rdw[512];
        __shared__ long long rds[512];
        rdw[tid] = dw;
        rds[tid] = dsi;
        __syncthreads();
#pragma unroll
        for (int st = 256; st > 0; st >>= 1) {
            if (tid < st) { rdw[tid] += rdw[tid + st]; rds[tid] += rds[tid + st]; }
            __syncthreads();
        }
        if (tid == 0) {
            double BN   = (double)B * (double)NCOLS;
            double wbce = rdw[0] / BN;                       // mean(w * bce)
            double cwl  = 1.0 - ((double)rds[0]) / BN;       // mean(1 - streak/N)
            out[0] = (float)(0.5 * wbce + 0.5 * cwl);
            g_count = 0;                                     // reset for next replay
        }
    }
}

extern "C" void kernel_launch(void* const* d_in, const int* in_sizes, int n_in,
                              void* d_out, int out_size)
{
    const float4* p4 = (const float4*)d_in[0];   // y_pred
    const float4* t4 = (const float4*)d_in[1];   // y_true
    const float4* w4 = (const float4*)d_in[2];   // depth_weights
    int total = in_sizes[0];
    int B = total / NCOLS;                       // 8192

    depth_loss_fused_kernel<<<NBLK, 512>>>(p4, t4, w4, (float*)d_out, B);
}

// round 10
// speedup vs baseline: 1.1285x; 1.1285x over previous
#include <cuda_runtime.h>
#include <cuda_bf16.h>

#define EPS   1e-6f
#define NCOLS 4096
#define MAXB  8192
#define NBLK  444          // 148 SMs x 3 resident CTAs (persistent grid)

// Per-row streaks, per-CTA bce partials, completion counter (graph-replay safe).
__device__ int   g_ps[MAXB];       // max streak per row
__device__ float g_pw[NBLK];       // per-CTA sum of depth_weights * bce
__device__ unsigned int g_count = 0;

// Combine left (ap,as,ab | len la) with right (bp,bs,bb | len lb); result in a*.
#define SEG_COMBINE(ap, as, ab, la, bp, bs, bb, lb)              \
    do {                                                         \
        int _np = ((ap) == (la)) ? (la) + (bp) : (ap);           \
        int _ns = ((bs) == (lb)) ? (lb) + (as) : (bs);           \
        int _nb = max(max((ab), (bb)), (as) + (bp));             \
        (ap) = _np; (as) = _ns; (ab) = _nb;                      \
    } while (0)

__device__ __forceinline__ void l2_prefetch(const void* p) {
    asm volatile("prefetch.global.L2 [%0];" :: "l"(p));
}

// Persistent CTAs: 512 threads (16 warps), each CTA strides over rows.
// Per-row barrier keeps all 16 warps on the SAME row -> dense contiguous
// 48KB bursts per row (locality; see R9 post-mortem). Next row's lines are
// L2-prefetched while the tree/barrier runs, so demand loads hit L2.
__global__ __launch_bounds__(512, 3)
void depth_loss_fused_kernel(const float4* __restrict__ p4,
                             const float4* __restrict__ t4,
                             const float4* __restrict__ w4,
                             float* __restrict__ out, int B)
{
    const int tid  = threadIdx.x;
    const int warp = tid >> 5;
    const int lane = tid & 31;
    const size_t rstride = (size_t)gridDim.x * (NCOLS / 4);   // float4s per row step

    __shared__ int shp[2][16], shs[2][16], shb[2][16];   // parity double-buffer
    __shared__ int s_isLast;

    float wacc = 0.0f;            // per-thread bce partial across all its rows
    int par = 0;

    for (int row = blockIdx.x; row < B; row += gridDim.x, par ^= 1) {
        const size_t base = (size_t)row * (NCOLS / 4) + warp * 64 + lane * 2;

        // front-batch all 6 LDG.128
        float4 pA = __ldcs(&p4[base]), pB = __ldcs(&p4[base + 1]);
        float4 tA = __ldcs(&t4[base]), tB = __ldcs(&t4[base + 1]);
        float4 wA = __ldcs(&w4[base]), wB = __ldcs(&w4[base + 1]);

        // L2-prefetch next row while this row's tree + barrier run
        if (row + (int)gridDim.x < B) {
            l2_prefetch(&p4[base + rstride]);
            l2_prefetch(&t4[base + rstride]);
            l2_prefetch(&w4[base + rstride]);
        }

        float pp[8] = {pA.x, pA.y, pA.z, pA.w, pB.x, pB.y, pB.z, pB.w};
        float tt[8] = {tA.x, tA.y, tA.z, tA.w, tB.x, tB.y, tB.z, tB.w};
        float ww[8] = {wA.x, wA.y, wA.z, wA.w, wB.x, wB.y, wB.z, wB.w};

        // leaf state over 8 contiguous elements (branch-free); bce into wacc
        int cur = 0, best = 0, pref = 0, all = 1;
#pragma unroll
        for (int e = 0; e < 8; e++) {
            bool tb = (tt[e] > 0.5f);
            bool pb = (pp[e] > 0.5f);
            int corr = (tb == pb) ? 1 : 0;
            float v = tb ? (pp[e] + EPS) : ((1.0f - pp[e]) + EPS);
            wacc = fmaf(ww[e], -__logf(v), wacc);
            cur  = corr ? (cur + 1) : 0;
            best = max(best, cur);
            all &= corr;
            pref += all;
        }
        int suf = cur;

        // warp tree: 8-elem leaves -> 256-elem warp segment (valid in lane 0)
#pragma unroll
        for (int s = 0; s < 5; s++) {
            int len = 8 << s;
            int op = __shfl_down_sync(0xffffffffu, pref, 1 << s);
            int os = __shfl_down_sync(0xffffffffu, suf,  1 << s);
            int ob = __shfl_down_sync(0xffffffffu, best, 1 << s);
            SEG_COMBINE(pref, suf, best, len, op, os, ob, len);
        }

        if (lane == 0) { shp[par][warp] = pref; shs[par][warp] = suf; shb[par][warp] = best; }
        __syncthreads();

        // tid0 combines this row while the other warps proceed to the next
        // row's loads (parity slot [par] is not rewritten until row+2, which
        // is fenced by row+1's barrier).
        if (tid == 0) {
            int ap = shp[par][0], as = shs[par][0], ab = shb[par][0];
#pragma unroll
            for (int wi = 1; wi < 16; wi++)
                SEG_COMBINE(ap, as, ab, 256 * wi, shp[par][wi], shs[par][wi], shb[par][wi], 256);
            g_ps[row] = ab;                     // plain STG; released by CTA-end fence
        }
    }

    // ---- CTA end: reduce per-thread bce partials, one fence+atomic per CTA ----
#pragma unroll
    for (int s = 16; s > 0; s >>= 1)
        wacc += __shfl_down_sync(0xffffffffu, wacc, s);
    __shared__ float shwf[16];
    if (lane == 0) shwf[warp] = wacc;
    __syncthreads();
    if (tid == 0) {
        float ws = shwf[0];
#pragma unroll
        for (int wi = 1; wi < 16; wi++) ws += shwf[wi];
        g_pw[blockIdx.x] = ws;
        __threadfence();                         // release partials + streaks
        unsigned int done = atomicAdd(&g_count, 1u);
        s_isLast = (done == (unsigned int)(gridDim.x - 1)) ? 1 : 0;
    }
    __syncthreads();

    // ---- last CTA: final deterministic reduction ----
    if (s_isLast) {
        __threadfence();   // acquire: see all CTAs' partials
        double dw = 0.0;
        long long dsi = 0;
        for (int i = tid; i < (int)gridDim.x; i += 512)
            dw += (double)g_pw[i];
        for (int r = tid; r < B; r += 2048) {
            int b0 = g_ps[r], b1 = g_ps[r + 512], b2 = g_ps[r + 1024], b3 = g_ps[r + 1536];
            dsi += (long long)b0 + b1 + b2 + b3;
        }
        __shared__ double    rdw[512];
        __shared__ long long rds[512];
        rdw[tid] = dw;
        rds[tid] = dsi;
        __syncthreads();
#pragma unroll
        for (int st = 256; st > 0; st >>= 1) {
            if (tid < st) { rdw[tid] += rdw[tid + st]; rds[tid] += rds[tid + st]; }
            __syncthreads();
        }
        if (tid == 0) {
            double BN   = (double)B * (double)NCOLS;
            double wbce = rdw[0] / BN;                       // mean(w * bce)
            double cwl  = 1.0 - ((double)rds[0]) / BN;       // mean(1 - streak/N)
            out[0] = (float)(0.5 * wbce + 0.5 * cwl);
            g_count = 0;                                     // reset for next replay
        }
    }
}

extern "C" void kernel_launch(void* const* d_in, const int* in_sizes, int n_in,
                              void* d_out, int out_size)
{
    const float4* p4 = (const float4*)d_in[0];   // y_pred
    const float4* t4 = (const float4*)d_in[1];   // y_true
    const float4* w4 = (const float4*)d_in[2];   // depth_weights
    int total = in_sizes[0];
    int B = total / NCOLS;                       // 8192

    depth_loss_fused_kernel<<<NBLK, 512>>>(p4, t4, w4, (float*)d_out, B);
}